// round 12
// baseline (speedup 1.0000x reference)
#include <cuda_runtime.h>
#include <cstdint>

#define WIN    100
#define H      64
#define AA     64
#define KK     8
#define NAPP   4
#define DT     0.1f
#define LN_EPS 1e-5f
#define TPB    128
#define SPC    64                 // samples per CTA
#define BMAX   32768

#define SWGT_FLOATS (WIN * AA)              // 6400: max of W_rec(4096)/Wx0(4096)/We_t(6400)
#define SHS_FLOATS  (4 * H * 16)            // 4096 (per-warp h/x slabs)
#define DYN_BYTES   ((SWGT_FLOATS + SHS_FLOATS) * sizeof(float))   // 41,984 B

// gmem scratch (static __device__ allowed; no runtime alloc)
__device__ float g_yt[WIN * BMAX];           // y transposed [t][b]
__device__ float g_wet[KK * WIN * AA];       // We transposed [k][t][a]
__device__ float g_wrt[KK * AA * AA];        // Wr transposed [k][i][a]
__device__ float g_wx0t[AA * AA];            // Wx0 transposed [i][a]

__device__ __forceinline__ float softplus_f(float v) {
    return (v > 20.f) ? v : log1pf(expf(v));
}

// HW tanh (MUFU.TANH); measured rel_err impact negligible (3.29e-7).
__device__ __forceinline__ float tanh_fast(float x) {
    float r;
    asm("tanh.approx.f32 %0, %1;" : "=f"(r) : "f"(x));
    return r;
}

// Pack {a,a} into a b64 ONCE; reuse across many ffma2.
__device__ __forceinline__ uint64_t dup2(float a) {
    uint64_t r;
    asm("mov.b64 %0, {%1, %1};" : "=l"(r) : "f"(a));
    return r;
}

// d += ap * {bx,by} on packed f32x2 (SASS FFMA2). ap pre-duplicated.
__device__ __forceinline__ void ffma2p(float2& d, uint64_t ap, float bx, float by) {
    asm("{\n\t"
        ".reg .b64 rb, rd;\n\t"
        "mov.b64 rb, {%3, %4};\n\t"
        "mov.b64 rd, {%0, %1};\n\t"
        "fma.rn.f32x2 rd, %2, rb, rd;\n\t"
        "mov.b64 {%0, %1}, rd;\n\t"
        "}"
        : "+f"(d.x), "+f"(d.y)
        : "l"(ap), "f"(bx), "f"(by));
}

// ---------------- prep kernels ----------------
__global__ void transpose_y_kernel(const float* __restrict__ y, int B) {
    __shared__ float tile[32][33];
    const int bb = blockIdx.x * 32;
    const int tt = blockIdx.y * 32;
    const int tx = threadIdx.x, ty = threadIdx.y;       // 32 x 8
    for (int r = ty; r < 32; r += 8) {
        const int b = bb + r, t = tt + tx;
        tile[r][tx] = (b < B && t < WIN) ? y[(long)b * WIN + t] : 0.f;
    }
    __syncthreads();
    for (int r = ty; r < 32; r += 8) {
        const int t = tt + r, b = bb + tx;
        if (t < WIN && b < B) g_yt[t * BMAX + b] = tile[tx][r];
    }
}

__global__ void prep_weights_kernel(const float* __restrict__ We,
                                    const float* __restrict__ Wr,
                                    const float* __restrict__ Wx0) {
    const int idx = blockIdx.x * blockDim.x + threadIdx.x;
    if (idx < KK * WIN * AA) {
        const int k = idx / (WIN * AA);
        const int rem = idx - k * WIN * AA;
        const int t = rem >> 6, a = rem & 63;
        g_wet[idx] = We[k * AA * WIN + a * WIN + t];
        return;
    }
    const int i2 = idx - KK * WIN * AA;
    if (i2 >= 0 && i2 < KK * AA * AA) {
        const int k = i2 >> 12;
        const int rem = i2 & 4095;
        const int i = rem >> 6, a = rem & 63;
        g_wrt[i2] = Wr[k * AA * AA + a * AA + i];
        return;
    }
    const int i3 = i2 - KK * AA * AA;
    if (i3 >= 0 && i3 < AA * AA) {
        const int i = i3 >> 6, a = i3 & 63;
        g_wx0t[i3] = Wx0[a * AA + i];
    }
}

// ---------------- main kernel ----------------
__global__ __launch_bounds__(TPB, 4)       // 4 CTAs/SM -> 592 slots >= 512 CTAs: SINGLE WAVE
void pinn_main_kernel(
    const float* __restrict__ w_in,
    const float* __restrict__ b_in,
    const float* __restrict__ tau_param,
    const float* __restrict__ W_rec,
    const float* __restrict__ ln_w,
    const float* __restrict__ ln_b,
    const float* __restrict__ bx0,
    const float* __restrict__ be,
    const float* __restrict__ thr,
    const float* __restrict__ head_W,
    const float* __restrict__ head_b,
    float* __restrict__ out_power,
    float* __restrict__ out_x,
    int B)
{
    extern __shared__ __align__(16) float smem[];
    float* sWgt = smem;                         // W_rec / Wx0 / We_t (phase-dependent)
    float* sHs  = smem + SWGT_FLOATS;           // 4 warps x (H*16) floats

    __shared__ float s_win[H], s_bin[H], s_lnw[H], s_lnb[H], s_dec[H];
    __shared__ float s_vec[AA], s_lam[AA], s_head[NAPP * AA], s_headb[NAPP];

    const int tid  = threadIdx.x;
    const int warp = tid >> 5, lane = tid & 31;
    const int cg   = lane & 7;            // channel group: ch [8cg, 8cg+8)
    const int sg   = lane >> 3;           // sample quad within warp
    const int c0   = cg * 8;
    const int s0   = blockIdx.x * SPC + warp * 16 + sg * 4;   // 4 consecutive samples
    const unsigned FULL = 0xffffffffu;

    float4* HsW = reinterpret_cast<float4*>(sHs + warp * (H * 16));
    // slot swizzle: f4-col for (row, sg) = sg ^ ((row>>3)&3)
    const int myslot = sg ^ (cg & 3);

    // ---- stage phase-1 weights + params ----
    for (int i = tid; i < H * H; i += TPB) sWgt[i] = W_rec[i];
    if (tid < H) {
        s_win[tid] = w_in[tid];
        s_bin[tid] = b_in[tid];
        s_lnw[tid] = ln_w[tid];
        s_lnb[tid] = ln_b[tid];
        s_dec[tid] = DT / softplus_f(tau_param[tid]);
    }
    for (int i = tid; i < NAPP * AA; i += TPB) s_head[i] = head_W[i];
    if (tid < NAPP) s_headb[tid] = head_b[tid];
    // zero my Hs rows
    {
        const float4 z4 = make_float4(0.f, 0.f, 0.f, 0.f);
        #pragma unroll
        for (int cc = 0; cc < 8; cc++)
            HsW[(c0 + cc) * 4 + myslot] = z4;
    }
    __syncthreads();

    // ================= Phase 1: LNN recurrence =================
    float2 hv2[4][4];   // h tile [sample][chpair]
    #pragma unroll
    for (int s = 0; s < 4; s++)
        #pragma unroll
        for (int cp = 0; cp < 4; cp++) hv2[s][cp] = make_float2(0.f, 0.f);

    {
        const float4* sW4 = reinterpret_cast<const float4*>(sWgt);
        const float2* s_win2 = reinterpret_cast<const float2*>(s_win);
        const float2* s_bin2 = reinterpret_cast<const float2*>(s_bin);
        const float2* s_lnw2 = reinterpret_cast<const float2*>(s_lnw);
        const float2* s_lnb2 = reinterpret_cast<const float2*>(s_lnb);
        const float2* s_dec2 = reinterpret_cast<const float2*>(s_dec);
        const int cp0 = c0 / 2;   // float2 index base for my 8 channels

        for (int t = 0; t < WIN; t++) {
            const float4 y4 = *reinterpret_cast<const float4*>(&g_yt[t * BMAX + s0]);
            float2 pre[4][4];
            #pragma unroll
            for (int cp = 0; cp < 4; cp++) {
                const float2 w2 = s_win2[cp0 + cp];
                const float2 b2 = s_bin2[cp0 + cp];
                pre[0][cp] = make_float2(fmaf(y4.x, w2.x, b2.x), fmaf(y4.x, w2.y, b2.y));
                pre[1][cp] = make_float2(fmaf(y4.y, w2.x, b2.x), fmaf(y4.y, w2.y, b2.y));
                pre[2][cp] = make_float2(fmaf(y4.z, w2.x, b2.x), fmaf(y4.z, w2.y, b2.y));
                pre[3][cp] = make_float2(fmaf(y4.w, w2.x, b2.x), fmaf(y4.w, w2.y, b2.y));
            }
            // pre += h @ W_rec
            for (int q = 0; q < 8; q++) {
                const int sl = sg ^ (q & 3);
                #pragma unroll
                for (int r = 0; r < 8; r++) {
                    const int i = q * 8 + r;
                    const float4 hv = HsW[i * 4 + sl];
                    const uint64_t h0 = dup2(hv.x), h1 = dup2(hv.y);
                    const uint64_t h2 = dup2(hv.z), h3 = dup2(hv.w);
                    const float4 wa = sW4[i * 16 + cg * 2];
                    const float4 wb = sW4[i * 16 + cg * 2 + 1];
                    ffma2p(pre[0][0], h0, wa.x, wa.y); ffma2p(pre[0][1], h0, wa.z, wa.w);
                    ffma2p(pre[0][2], h0, wb.x, wb.y); ffma2p(pre[0][3], h0, wb.z, wb.w);
                    ffma2p(pre[1][0], h1, wa.x, wa.y); ffma2p(pre[1][1], h1, wa.z, wa.w);
                    ffma2p(pre[1][2], h1, wb.x, wb.y); ffma2p(pre[1][3], h1, wb.z, wb.w);
                    ffma2p(pre[2][0], h2, wa.x, wa.y); ffma2p(pre[2][1], h2, wa.z, wa.w);
                    ffma2p(pre[2][2], h2, wb.x, wb.y); ffma2p(pre[2][3], h2, wb.z, wb.w);
                    ffma2p(pre[3][0], h3, wa.x, wa.y); ffma2p(pre[3][1], h3, wa.z, wa.w);
                    ffma2p(pre[3][2], h3, wb.x, wb.y); ffma2p(pre[3][3], h3, wb.z, wb.w);
                }
            }
            // LN + tanh + Euler update (octet shfl reduction)
            #pragma unroll
            for (int s = 0; s < 4; s++) {
                float sm = 0.f, sq = 0.f;
                #pragma unroll
                for (int cp = 0; cp < 4; cp++) {
                    sm += pre[s][cp].x + pre[s][cp].y;
                    sq = fmaf(pre[s][cp].x, pre[s][cp].x, sq);
                    sq = fmaf(pre[s][cp].y, pre[s][cp].y, sq);
                }
                sm += __shfl_xor_sync(FULL, sm, 1, 32);
                sm += __shfl_xor_sync(FULL, sm, 2, 32);
                sm += __shfl_xor_sync(FULL, sm, 4, 32);
                sq += __shfl_xor_sync(FULL, sq, 1, 32);
                sq += __shfl_xor_sync(FULL, sq, 2, 32);
                sq += __shfl_xor_sync(FULL, sq, 4, 32);
                const float mean = sm * (1.f / H);
                const float var  = fmaf(-mean, mean, sq * (1.f / H));
                const float rstd = rsqrtf(var + LN_EPS);
                #pragma unroll
                for (int cp = 0; cp < 4; cp++) {
                    const float2 lw = s_lnw2[cp0 + cp];
                    const float2 lb = s_lnb2[cp0 + cp];
                    const float2 dc = s_dec2[cp0 + cp];
                    const float fx = tanh_fast(fmaf((pre[s][cp].x - mean) * rstd, lw.x, lb.x));
                    const float fy = tanh_fast(fmaf((pre[s][cp].y - mean) * rstd, lw.y, lb.y));
                    float hx = fmaf(DT, fx, fmaf(-dc.x, hv2[s][cp].x, hv2[s][cp].x));
                    float hy = fmaf(DT, fy, fmaf(-dc.y, hv2[s][cp].y, hv2[s][cp].y));
                    hv2[s][cp].x = fminf(10.f, fmaxf(-10.f, hx));
                    hv2[s][cp].y = fminf(10.f, fmaxf(-10.f, hy));
                }
            }
            // publish h to per-warp slab
            __syncwarp();
            #pragma unroll
            for (int cc = 0; cc < 8; cc++) {
                const int cp = cc >> 1;
                float4 v;
                if (cc & 1) v = make_float4(hv2[0][cp].y, hv2[1][cp].y, hv2[2][cp].y, hv2[3][cp].y);
                else        v = make_float4(hv2[0][cp].x, hv2[1][cp].x, hv2[2][cp].x, hv2[3][cp].x);
                HsW[(c0 + cc) * 4 + myslot] = v;
            }
            __syncwarp();
        }
    }

    // ================= Phase 2: x = h @ Wx0^T + bx0 =================
    __syncthreads();
    for (int i = tid; i < AA * AA; i += TPB) sWgt[i] = g_wx0t[i];
    if (tid < AA) s_vec[tid] = bx0[tid];
    __syncthreads();

    float2 xv[4][4];
    {
        const float4* sW4 = reinterpret_cast<const float4*>(sWgt);
        #pragma unroll
        for (int cp = 0; cp < 4; cp++) {
            const float2 b2 = make_float2(s_vec[c0 + 2 * cp], s_vec[c0 + 2 * cp + 1]);
            #pragma unroll
            for (int s = 0; s < 4; s++) xv[s][cp] = b2;
        }
        for (int q = 0; q < 8; q++) {
            const int sl = sg ^ (q & 3);
            #pragma unroll
            for (int r = 0; r < 8; r++) {
                const int i = q * 8 + r;
                const float4 hv = HsW[i * 4 + sl];
                const uint64_t h0 = dup2(hv.x), h1 = dup2(hv.y);
                const uint64_t h2 = dup2(hv.z), h3 = dup2(hv.w);
                const float4 wa = sW4[i * 16 + cg * 2];
                const float4 wb = sW4[i * 16 + cg * 2 + 1];
                ffma2p(xv[0][0], h0, wa.x, wa.y); ffma2p(xv[0][1], h0, wa.z, wa.w);
                ffma2p(xv[0][2], h0, wb.x, wb.y); ffma2p(xv[0][3], h0, wb.z, wb.w);
                ffma2p(xv[1][0], h1, wa.x, wa.y); ffma2p(xv[1][1], h1, wa.z, wa.w);
                ffma2p(xv[1][2], h1, wb.x, wb.y); ffma2p(xv[1][3], h1, wb.z, wb.w);
                ffma2p(xv[2][0], h2, wa.x, wa.y); ffma2p(xv[2][1], h2, wa.z, wa.w);
                ffma2p(xv[2][2], h2, wb.x, wb.y); ffma2p(xv[2][3], h2, wb.z, wb.w);
                ffma2p(xv[3][0], h3, wa.x, wa.y); ffma2p(xv[3][1], h3, wa.z, wa.w);
                ffma2p(xv[3][2], h3, wb.x, wb.y); ffma2p(xv[3][3], h3, wb.z, wb.w);
            }
        }
    }
    // publish x into slab (reuse as Xs)
    __syncwarp();
    #pragma unroll
    for (int cc = 0; cc < 8; cc++) {
        const int cp = cc >> 1;
        float4 v;
        if (cc & 1) v = make_float4(xv[0][cp].y, xv[1][cp].y, xv[2][cp].y, xv[3][cp].y);
        else        v = make_float4(xv[0][cp].x, xv[1][cp].x, xv[2][cp].x, xv[3][cp].x);
        HsW[(c0 + cc) * 4 + myslot] = v;
    }
    __syncwarp();

    // ================= Phase 3: ISTA iterations =================
    for (int k = 0; k < KK; k++) {
        __syncthreads();
        {
            // stage We_t only; Wr read from gmem (L2 broadcast across all CTAs)
            const float4* wet4 = reinterpret_cast<const float4*>(g_wet + k * WIN * AA);
            float4* d4 = reinterpret_cast<float4*>(sWgt);
            for (int i = tid; i < (WIN * AA) / 4; i += TPB) d4[i] = wet4[i];
            if (tid < AA) {
                s_vec[tid] = be[k * AA + tid];
                s_lam[tid] = softplus_f(thr[k * AA + tid]);
            }
        }
        __syncthreads();

        const float4* sWe4 = reinterpret_cast<const float4*>(sWgt);
        const float4* gWr4 = reinterpret_cast<const float4*>(g_wrt + k * AA * AA);

        float2 z[4][4];
        #pragma unroll
        for (int cp = 0; cp < 4; cp++) {
            const float2 b2 = make_float2(s_vec[c0 + 2 * cp], s_vec[c0 + 2 * cp + 1]);
            #pragma unroll
            for (int s = 0; s < 4; s++) z[s][cp] = b2;
        }
        // z += y @ We_k^T
        #pragma unroll 4
        for (int t = 0; t < WIN; t++) {
            const float4 y4 = *reinterpret_cast<const float4*>(&g_yt[t * BMAX + s0]);
            const uint64_t q0 = dup2(y4.x), q1 = dup2(y4.y);
            const uint64_t q2 = dup2(y4.z), q3 = dup2(y4.w);
            const float4 wa = sWe4[t * 16 + cg * 2];
            const float4 wb = sWe4[t * 16 + cg * 2 + 1];
            ffma2p(z[0][0], q0, wa.x, wa.y); ffma2p(z[0][1], q0, wa.z, wa.w);
            ffma2p(z[0][2], q0, wb.x, wb.y); ffma2p(z[0][3], q0, wb.z, wb.w);
            ffma2p(z[1][0], q1, wa.x, wa.y); ffma2p(z[1][1], q1, wa.z, wa.w);
            ffma2p(z[1][2], q1, wb.x, wb.y); ffma2p(z[1][3], q1, wb.z, wb.w);
            ffma2p(z[2][0], q2, wa.x, wa.y); ffma2p(z[2][1], q2, wa.z, wa.w);
            ffma2p(z[2][2], q2, wb.x, wb.y); ffma2p(z[2][3], q2, wb.z, wb.w);
            ffma2p(z[3][0], q3, wa.x, wa.y); ffma2p(z[3][1], q3, wa.z, wa.w);
            ffma2p(z[3][2], q3, wb.x, wb.y); ffma2p(z[3][3], q3, wb.z, wb.w);
        }
        // z += x @ Wr_k^T  (Xs in slab, Wr from gmem)
        for (int q = 0; q < 8; q++) {
            const int sl = sg ^ (q & 3);
            #pragma unroll
            for (int r = 0; r < 8; r++) {
                const int i = q * 8 + r;
                const float4 hv = HsW[i * 4 + sl];
                const uint64_t h0 = dup2(hv.x), h1 = dup2(hv.y);
                const uint64_t h2 = dup2(hv.z), h3 = dup2(hv.w);
                const float4 wa = __ldg(&gWr4[i * 16 + cg * 2]);
                const float4 wb = __ldg(&gWr4[i * 16 + cg * 2 + 1]);
                ffma2p(z[0][0], h0, wa.x, wa.y); ffma2p(z[0][1], h0, wa.z, wa.w);
                ffma2p(z[0][2], h0, wb.x, wb.y); ffma2p(z[0][3], h0, wb.z, wb.w);
                ffma2p(z[1][0], h1, wa.x, wa.y); ffma2p(z[1][1], h1, wa.z, wa.w);
                ffma2p(z[1][2], h1, wb.x, wb.y); ffma2p(z[1][3], h1, wb.z, wb.w);
                ffma2p(z[2][0], h2, wa.x, wa.y); ffma2p(z[2][1], h2, wa.z, wa.w);
                ffma2p(z[2][2], h2, wb.x, wb.y); ffma2p(z[2][3], h2, wb.z, wb.w);
                ffma2p(z[3][0], h3, wa.x, wa.y); ffma2p(z[3][1], h3, wa.z, wa.w);
                ffma2p(z[3][2], h3, wb.x, wb.y); ffma2p(z[3][3], h3, wb.z, wb.w);
            }
        }
        // soft threshold -> xv
        #pragma unroll
        for (int cp = 0; cp < 4; cp++) {
            const float2 lam2 = make_float2(s_lam[c0 + 2 * cp], s_lam[c0 + 2 * cp + 1]);
            #pragma unroll
            for (int s = 0; s < 4; s++) {
                const float zx = z[s][cp].x, zy = z[s][cp].y;
                xv[s][cp].x = copysignf(fmaxf(fabsf(zx) - lam2.x, 0.f), zx);
                xv[s][cp].y = copysignf(fmaxf(fabsf(zy) - lam2.y, 0.f), zy);
            }
        }
        // publish x
        __syncwarp();
        #pragma unroll
        for (int cc = 0; cc < 8; cc++) {
            const int cp = cc >> 1;
            float4 v;
            if (cc & 1) v = make_float4(xv[0][cp].y, xv[1][cp].y, xv[2][cp].y, xv[3][cp].y);
            else        v = make_float4(xv[0][cp].x, xv[1][cp].x, xv[2][cp].x, xv[3][cp].x);
            HsW[(c0 + cc) * 4 + myslot] = v;
        }
        __syncwarp();
    }

    // ================= Phase 4: heads + outputs =================
    {
        float p[4][NAPP];
        #pragma unroll
        for (int n = 0; n < NAPP; n++) {
            #pragma unroll
            for (int s = 0; s < 4; s++) {
                float acc = 0.f;
                #pragma unroll
                for (int cp = 0; cp < 4; cp++) {
                    acc = fmaf(xv[s][cp].x, s_head[n * AA + c0 + 2 * cp], acc);
                    acc = fmaf(xv[s][cp].y, s_head[n * AA + c0 + 2 * cp + 1], acc);
                }
                acc += __shfl_xor_sync(FULL, acc, 1, 32);
                acc += __shfl_xor_sync(FULL, acc, 2, 32);
                acc += __shfl_xor_sync(FULL, acc, 4, 32);
                p[s][n] = acc;
            }
        }
        #pragma unroll
        for (int s = 0; s < 4; s++) {
            const int b = s0 + s;
            if (b < B) {
                if (cg == 0) {
                    float4 pw = make_float4(p[s][0] + s_headb[0], p[s][1] + s_headb[1],
                                            p[s][2] + s_headb[2], p[s][3] + s_headb[3]);
                    *reinterpret_cast<float4*>(out_power + (long)b * NAPP) = pw;
                }
                float4* xo = reinterpret_cast<float4*>(out_x + (long)b * AA + c0);
                xo[0] = make_float4(xv[s][0].x, xv[s][0].y, xv[s][1].x, xv[s][1].y);
                xo[1] = make_float4(xv[s][2].x, xv[s][2].y, xv[s][3].x, xv[s][3].y);
            }
        }
    }
}

extern "C" void kernel_launch(void* const* d_in, const int* in_sizes, int n_in,
                              void* d_out, int out_size)
{
    const float* y         = (const float*)d_in[0];
    const float* w_in      = (const float*)d_in[1];
    const float* b_in      = (const float*)d_in[2];
    const float* tau_param = (const float*)d_in[3];
    const float* W_rec     = (const float*)d_in[4];
    const float* ln_w      = (const float*)d_in[5];
    const float* ln_b      = (const float*)d_in[6];
    const float* Wx0       = (const float*)d_in[7];
    const float* bx0       = (const float*)d_in[8];
    const float* We        = (const float*)d_in[9];
    const float* be        = (const float*)d_in[10];
    const float* Wr        = (const float*)d_in[11];
    const float* thr       = (const float*)d_in[12];
    const float* head_W    = (const float*)d_in[13];
    const float* head_b    = (const float*)d_in[14];

    const int B = in_sizes[0] / WIN;

    float* out       = (float*)d_out;
    float* out_power = out;                      // (B, NAPP) first
    float* out_x     = out + (size_t)B * NAPP;   // (B, A) second

    // prep: transpose y and weights into gmem scratch
    {
        dim3 blk(32, 8);
        dim3 grd((B + 31) / 32, (WIN + 31) / 32);
        transpose_y_kernel<<<grd, blk>>>(y, B);
    }
    {
        const int total = KK * WIN * AA + KK * AA * AA + AA * AA;
        prep_weights_kernel<<<(total + 255) / 256, 256>>>(We, Wr, Wx0);
    }

    cudaFuncSetAttribute(pinn_main_kernel,
                         cudaFuncAttributeMaxDynamicSharedMemorySize,
                         (int)DYN_BYTES);

    const int grid = (B + SPC - 1) / SPC;
    pinn_main_kernel<<<grid, TPB, DYN_BYTES>>>(
        w_in, b_in, tau_param, W_rec, ln_w, ln_b,
        bx0, be, thr, head_W, head_b,
        out_power, out_x, B);
}

// round 13
// speedup vs baseline: 1.0303x; 1.0303x over previous
#include <cuda_runtime.h>
#include <cstdint>

#define WIN    100
#define H      64
#define AA     64
#define KK     8
#define NAPP   4
#define DT     0.1f
#define LN_EPS 1e-5f
#define TPB    128
#define SPC    64                 // samples per CTA
#define BMAX   32768

#define SWGT_FLOATS (WIN * AA + AA * AA)    // 10496
#define SHS_FLOATS  (4 * H * 16)            // 4096 (per-warp h/x slabs)
#define DYN_BYTES   ((SWGT_FLOATS + SHS_FLOATS) * sizeof(float))   // 58,368 B

// gmem scratch (static __device__ allowed; no runtime alloc)
__device__ float g_yt[WIN * BMAX];           // y transposed [t][b]
__device__ float g_wet[KK * WIN * AA];       // We transposed [k][t][a]
__device__ float g_wrt[KK * AA * AA];        // Wr transposed [k][i][a]
__device__ float g_wx0t[AA * AA];            // Wx0 transposed [i][a]

__device__ __forceinline__ float softplus_f(float v) {
    return (v > 20.f) ? v : log1pf(expf(v));
}

// HW tanh (MUFU.TANH); measured rel_err impact negligible (3.29e-7).
__device__ __forceinline__ float tanh_fast(float x) {
    float r;
    asm("tanh.approx.f32 %0, %1;" : "=f"(r) : "f"(x));
    return r;
}

// ---- packed f32x2 primitives: operands live as uint64_t, NO per-FMA movs ----
__device__ __forceinline__ uint64_t dup2(float a) {          // {a,a}
    uint64_t r;
    asm("mov.b64 %0, {%1, %1};" : "=l"(r) : "f"(a));
    return r;
}
__device__ __forceinline__ uint64_t pk2(float x, float y) {  // {x,y}
    uint64_t r;
    asm("mov.b64 %0, {%1, %2};" : "=l"(r) : "f"(x), "f"(y));
    return r;
}
__device__ __forceinline__ void upk2(float& x, float& y, uint64_t d) {
    asm("mov.b64 {%0, %1}, %2;" : "=f"(x), "=f"(y) : "l"(d));
}
// d += a * b   — exactly ONE SASS instruction (FFMA2)
__device__ __forceinline__ void ffma2(uint64_t& d, uint64_t a, uint64_t b) {
    asm("fma.rn.f32x2 %0, %1, %2, %0;" : "+l"(d) : "l"(a), "l"(b));
}

// ---------------- merged prep kernel (one launch) ----------------
__global__ void prep_all_kernel(const float* __restrict__ y,
                                const float* __restrict__ We,
                                const float* __restrict__ Wr,
                                const float* __restrict__ Wx0,
                                int B, int nBB, int nYBlocks) {
    __shared__ float tile[32][33];
    const int tid = threadIdx.x;
    if ((int)blockIdx.x < nYBlocks) {
        // y transpose tile
        const int bb = (blockIdx.x % nBB) * 32;
        const int tt = (blockIdx.x / nBB) * 32;
        const int tx = tid & 31, ty = tid >> 5;           // 32 x 8
        for (int r = ty; r < 32; r += 8) {
            const int b = bb + r, t = tt + tx;
            tile[r][tx] = (b < B && t < WIN) ? y[(long)b * WIN + t] : 0.f;
        }
        __syncthreads();
        for (int r = ty; r < 32; r += 8) {
            const int t = tt + r, b = bb + tx;
            if (t < WIN && b < B) g_yt[t * BMAX + b] = tile[tx][r];
        }
        return;
    }
    // weight transposes (flat)
    const int idx = (blockIdx.x - nYBlocks) * blockDim.x + tid;
    if (idx < KK * WIN * AA) {
        const int k = idx / (WIN * AA);
        const int rem = idx - k * WIN * AA;
        const int t = rem >> 6, a = rem & 63;
        g_wet[idx] = We[k * AA * WIN + a * WIN + t];
        return;
    }
    const int i2 = idx - KK * WIN * AA;
    if (i2 >= 0 && i2 < KK * AA * AA) {
        const int k = i2 >> 12;
        const int rem = i2 & 4095;
        const int i = rem >> 6, a = rem & 63;
        g_wrt[i2] = Wr[k * AA * AA + a * AA + i];
        return;
    }
    const int i3 = i2 - KK * AA * AA;
    if (i3 >= 0 && i3 < AA * AA) {
        const int i = i3 >> 6, a = i3 & 63;
        g_wx0t[i3] = Wx0[a * AA + i];
    }
}

// ---------------- main kernel ----------------
__global__ __launch_bounds__(TPB, 3)
void pinn_main_kernel(
    const float* __restrict__ w_in,
    const float* __restrict__ b_in,
    const float* __restrict__ tau_param,
    const float* __restrict__ W_rec,
    const float* __restrict__ ln_w,
    const float* __restrict__ ln_b,
    const float* __restrict__ bx0,
    const float* __restrict__ be,
    const float* __restrict__ thr,
    const float* __restrict__ head_W,
    const float* __restrict__ head_b,
    float* __restrict__ out_power,
    float* __restrict__ out_x,
    int B)
{
    extern __shared__ __align__(16) float smem[];
    float* sWgt = smem;                         // W_rec/Wx0 | We_t+Wr_t
    float* sHs  = smem + SWGT_FLOATS;           // 4 warps x (H*16) floats

    __shared__ float s_win[H], s_bin[H], s_lnw[H], s_lnb[H], s_dec[H];
    __shared__ float s_vec[AA], s_lam[AA], s_head[NAPP * AA], s_headb[NAPP];

    const int tid  = threadIdx.x;
    const int warp = tid >> 5, lane = tid & 31;
    const int cg   = lane & 7;            // channel group: ch [8cg, 8cg+8)
    const int sg   = lane >> 3;           // sample quad within warp
    const int c0   = cg * 8;
    const int s0   = blockIdx.x * SPC + warp * 16 + sg * 4;
    const unsigned FULL = 0xffffffffu;

    float4* HsW = reinterpret_cast<float4*>(sHs + warp * (H * 16));
    const int myslot = sg ^ (cg & 3);     // slot swizzle matches read side sg^(q&3)

    // ---- stage phase-1 weights + params ----
    for (int i = tid; i < H * H; i += TPB) sWgt[i] = W_rec[i];
    if (tid < H) {
        s_win[tid] = w_in[tid];
        s_bin[tid] = b_in[tid];
        s_lnw[tid] = ln_w[tid];
        s_lnb[tid] = ln_b[tid];
        s_dec[tid] = DT / softplus_f(tau_param[tid]);
    }
    for (int i = tid; i < NAPP * AA; i += TPB) s_head[i] = head_W[i];
    if (tid < NAPP) s_headb[tid] = head_b[tid];
    {
        const float4 z4 = make_float4(0.f, 0.f, 0.f, 0.f);
        #pragma unroll
        for (int cc = 0; cc < 8; cc++)
            HsW[(c0 + cc) * 4 + myslot] = z4;
    }
    __syncthreads();

    // hoist per-channel constants (win/bin packed; ln/dec as float2)
    uint64_t win2p[4], bin2p[4];
    float2 lnw2[4], lnb2[4], dec2[4];
    #pragma unroll
    for (int cp = 0; cp < 4; cp++) {
        const int c = c0 + 2 * cp;
        win2p[cp] = pk2(s_win[c], s_win[c + 1]);
        bin2p[cp] = pk2(s_bin[c], s_bin[c + 1]);
        lnw2[cp] = make_float2(s_lnw[c], s_lnw[c + 1]);
        lnb2[cp] = make_float2(s_lnb[c], s_lnb[c + 1]);
        dec2[cp] = make_float2(s_dec[c], s_dec[c + 1]);
    }

    // ================= Phase 1: LNN recurrence =================
    float2 hv2[4][4];
    #pragma unroll
    for (int s = 0; s < 4; s++)
        #pragma unroll
        for (int cp = 0; cp < 4; cp++) hv2[s][cp] = make_float2(0.f, 0.f);

    {
        const ulonglong2* sWu = reinterpret_cast<const ulonglong2*>(sWgt);
        for (int t = 0; t < WIN; t++) {
            const float4 y4 = *reinterpret_cast<const float4*>(&g_yt[t * BMAX + s0]);
            const uint64_t ys[4] = { dup2(y4.x), dup2(y4.y), dup2(y4.z), dup2(y4.w) };
            uint64_t pre[4][4];
            #pragma unroll
            for (int s = 0; s < 4; s++)
                #pragma unroll
                for (int cp = 0; cp < 4; cp++) {
                    pre[s][cp] = bin2p[cp];
                    ffma2(pre[s][cp], ys[s], win2p[cp]);
                }
            // pre += h @ W_rec : per i = 1 slab LDS.128 + 4 dup + 2 weight LDS.128 + 16 FFMA2
            for (int q = 0; q < 8; q++) {
                const int sl = sg ^ (q & 3);
                #pragma unroll
                for (int r = 0; r < 8; r++) {
                    const int i = q * 8 + r;
                    const float4 hv = HsW[i * 4 + sl];
                    const uint64_t h0 = dup2(hv.x), h1 = dup2(hv.y);
                    const uint64_t h2 = dup2(hv.z), h3 = dup2(hv.w);
                    const ulonglong2 wa = sWu[i * 16 + cg * 2];        // pairs {c0..c0+3}
                    const ulonglong2 wb = sWu[i * 16 + cg * 2 + 1];    // pairs {c0+4..c0+7}
                    ffma2(pre[0][0], h0, wa.x); ffma2(pre[0][1], h0, wa.y);
                    ffma2(pre[0][2], h0, wb.x); ffma2(pre[0][3], h0, wb.y);
                    ffma2(pre[1][0], h1, wa.x); ffma2(pre[1][1], h1, wa.y);
                    ffma2(pre[1][2], h1, wb.x); ffma2(pre[1][3], h1, wb.y);
                    ffma2(pre[2][0], h2, wa.x); ffma2(pre[2][1], h2, wa.y);
                    ffma2(pre[2][2], h2, wb.x); ffma2(pre[2][3], h2, wb.y);
                    ffma2(pre[3][0], h3, wa.x); ffma2(pre[3][1], h3, wa.y);
                    ffma2(pre[3][2], h3, wb.x); ffma2(pre[3][3], h3, wb.y);
                }
            }
            // LN + tanh + Euler (octet shfl reduction)
            #pragma unroll
            for (int s = 0; s < 4; s++) {
                float px[4], py[4];
                float sm = 0.f, sq = 0.f;
                #pragma unroll
                for (int cp = 0; cp < 4; cp++) {
                    upk2(px[cp], py[cp], pre[s][cp]);
                    sm += px[cp] + py[cp];
                    sq = fmaf(px[cp], px[cp], sq);
                    sq = fmaf(py[cp], py[cp], sq);
                }
                sm += __shfl_xor_sync(FULL, sm, 1, 32);
                sm += __shfl_xor_sync(FULL, sm, 2, 32);
                sm += __shfl_xor_sync(FULL, sm, 4, 32);
                sq += __shfl_xor_sync(FULL, sq, 1, 32);
                sq += __shfl_xor_sync(FULL, sq, 2, 32);
                sq += __shfl_xor_sync(FULL, sq, 4, 32);
                const float mean = sm * (1.f / H);
                const float var  = fmaf(-mean, mean, sq * (1.f / H));
                const float rstd = rsqrtf(var + LN_EPS);
                #pragma unroll
                for (int cp = 0; cp < 4; cp++) {
                    const float fx = tanh_fast(fmaf((px[cp] - mean) * rstd, lnw2[cp].x, lnb2[cp].x));
                    const float fy = tanh_fast(fmaf((py[cp] - mean) * rstd, lnw2[cp].y, lnb2[cp].y));
                    float hx = fmaf(DT, fx, fmaf(-dec2[cp].x, hv2[s][cp].x, hv2[s][cp].x));
                    float hy = fmaf(DT, fy, fmaf(-dec2[cp].y, hv2[s][cp].y, hv2[s][cp].y));
                    hv2[s][cp].x = fminf(10.f, fmaxf(-10.f, hx));
                    hv2[s][cp].y = fminf(10.f, fmaxf(-10.f, hy));
                }
            }
            // publish h to per-warp slab
            __syncwarp();
            #pragma unroll
            for (int cc = 0; cc < 8; cc++) {
                const int cp = cc >> 1;
                float4 v;
                if (cc & 1) v = make_float4(hv2[0][cp].y, hv2[1][cp].y, hv2[2][cp].y, hv2[3][cp].y);
                else        v = make_float4(hv2[0][cp].x, hv2[1][cp].x, hv2[2][cp].x, hv2[3][cp].x);
                HsW[(c0 + cc) * 4 + myslot] = v;
            }
            __syncwarp();
        }
    }

    // ================= Phase 2: x = h @ Wx0^T + bx0 =================
    __syncthreads();
    for (int i = tid; i < AA * AA; i += TPB) sWgt[i] = g_wx0t[i];
    if (tid < AA) s_vec[tid] = bx0[tid];
    __syncthreads();

    float2 xv[4][4];
    {
        const ulonglong2* sWu = reinterpret_cast<const ulonglong2*>(sWgt);
        uint64_t xp[4][4];
        #pragma unroll
        for (int cp = 0; cp < 4; cp++) {
            const uint64_t b2 = pk2(s_vec[c0 + 2 * cp], s_vec[c0 + 2 * cp + 1]);
            #pragma unroll
            for (int s = 0; s < 4; s++) xp[s][cp] = b2;
        }
        for (int q = 0; q < 8; q++) {
            const int sl = sg ^ (q & 3);
            #pragma unroll
            for (int r = 0; r < 8; r++) {
                const int i = q * 8 + r;
                const float4 hv = HsW[i * 4 + sl];
                const uint64_t h0 = dup2(hv.x), h1 = dup2(hv.y);
                const uint64_t h2 = dup2(hv.z), h3 = dup2(hv.w);
                const ulonglong2 wa = sWu[i * 16 + cg * 2];
                const ulonglong2 wb = sWu[i * 16 + cg * 2 + 1];
                ffma2(xp[0][0], h0, wa.x); ffma2(xp[0][1], h0, wa.y);
                ffma2(xp[0][2], h0, wb.x); ffma2(xp[0][3], h0, wb.y);
                ffma2(xp[1][0], h1, wa.x); ffma2(xp[1][1], h1, wa.y);
                ffma2(xp[1][2], h1, wb.x); ffma2(xp[1][3], h1, wb.y);
                ffma2(xp[2][0], h2, wa.x); ffma2(xp[2][1], h2, wa.y);
                ffma2(xp[2][2], h2, wb.x); ffma2(xp[2][3], h2, wb.y);
                ffma2(xp[3][0], h3, wa.x); ffma2(xp[3][1], h3, wa.y);
                ffma2(xp[3][2], h3, wb.x); ffma2(xp[3][3], h3, wb.y);
            }
        }
        #pragma unroll
        for (int s = 0; s < 4; s++)
            #pragma unroll
            for (int cp = 0; cp < 4; cp++)
                upk2(xv[s][cp].x, xv[s][cp].y, xp[s][cp]);
    }
    // publish x into slab
    __syncwarp();
    #pragma unroll
    for (int cc = 0; cc < 8; cc++) {
        const int cp = cc >> 1;
        float4 v;
        if (cc & 1) v = make_float4(xv[0][cp].y, xv[1][cp].y, xv[2][cp].y, xv[3][cp].y);
        else        v = make_float4(xv[0][cp].x, xv[1][cp].x, xv[2][cp].x, xv[3][cp].x);
        HsW[(c0 + cc) * 4 + myslot] = v;
    }
    __syncwarp();

    // ================= Phase 3: ISTA iterations =================
    for (int k = 0; k < KK; k++) {
        __syncthreads();
        {
            const float4* wet4 = reinterpret_cast<const float4*>(g_wet + k * WIN * AA);
            const float4* wrt4 = reinterpret_cast<const float4*>(g_wrt + k * AA * AA);
            float4* d4 = reinterpret_cast<float4*>(sWgt);
            for (int i = tid; i < (WIN * AA) / 4; i += TPB) d4[i] = wet4[i];
            float4* e4 = reinterpret_cast<float4*>(sWgt + WIN * AA);
            for (int i = tid; i < (AA * AA) / 4; i += TPB) e4[i] = wrt4[i];
            if (tid < AA) {
                s_vec[tid] = be[k * AA + tid];
                s_lam[tid] = softplus_f(thr[k * AA + tid]);
            }
        }
        __syncthreads();

        const ulonglong2* sWeu = reinterpret_cast<const ulonglong2*>(sWgt);
        const ulonglong2* sWru = reinterpret_cast<const ulonglong2*>(sWgt + WIN * AA);

        uint64_t z[4][4];
        #pragma unroll
        for (int cp = 0; cp < 4; cp++) {
            const uint64_t b2 = pk2(s_vec[c0 + 2 * cp], s_vec[c0 + 2 * cp + 1]);
            #pragma unroll
            for (int s = 0; s < 4; s++) z[s][cp] = b2;
        }
        // z += y @ We_k^T
        #pragma unroll 4
        for (int t = 0; t < WIN; t++) {
            const float4 y4 = *reinterpret_cast<const float4*>(&g_yt[t * BMAX + s0]);
            const uint64_t q0 = dup2(y4.x), q1 = dup2(y4.y);
            const uint64_t q2 = dup2(y4.z), q3 = dup2(y4.w);
            const ulonglong2 wa = sWeu[t * 16 + cg * 2];
            const ulonglong2 wb = sWeu[t * 16 + cg * 2 + 1];
            ffma2(z[0][0], q0, wa.x); ffma2(z[0][1], q0, wa.y);
            ffma2(z[0][2], q0, wb.x); ffma2(z[0][3], q0, wb.y);
            ffma2(z[1][0], q1, wa.x); ffma2(z[1][1], q1, wa.y);
            ffma2(z[1][2], q1, wb.x); ffma2(z[1][3], q1, wb.y);
            ffma2(z[2][0], q2, wa.x); ffma2(z[2][1], q2, wa.y);
            ffma2(z[2][2], q2, wb.x); ffma2(z[2][3], q2, wb.y);
            ffma2(z[3][0], q3, wa.x); ffma2(z[3][1], q3, wa.y);
            ffma2(z[3][2], q3, wb.x); ffma2(z[3][3], q3, wb.y);
        }
        // z += x @ Wr_k^T
        for (int q = 0; q < 8; q++) {
            const int sl = sg ^ (q & 3);
            #pragma unroll
            for (int r = 0; r < 8; r++) {
                const int i = q * 8 + r;
                const float4 hv = HsW[i * 4 + sl];
                const uint64_t h0 = dup2(hv.x), h1 = dup2(hv.y);
                const uint64_t h2 = dup2(hv.z), h3 = dup2(hv.w);
                const ulonglong2 wa = sWru[i * 16 + cg * 2];
                const ulonglong2 wb = sWru[i * 16 + cg * 2 + 1];
                ffma2(z[0][0], h0, wa.x); ffma2(z[0][1], h0, wa.y);
                ffma2(z[0][2], h0, wb.x); ffma2(z[0][3], h0, wb.y);
                ffma2(z[1][0], h1, wa.x); ffma2(z[1][1], h1, wa.y);
                ffma2(z[1][2], h1, wb.x); ffma2(z[1][3], h1, wb.y);
                ffma2(z[2][0], h2, wa.x); ffma2(z[2][1], h2, wa.y);
                ffma2(z[2][2], h2, wb.x); ffma2(z[2][3], h2, wb.y);
                ffma2(z[3][0], h3, wa.x); ffma2(z[3][1], h3, wa.y);
                ffma2(z[3][2], h3, wb.x); ffma2(z[3][3], h3, wb.y);
            }
        }
        // soft threshold -> xv (scalar)
        #pragma unroll
        for (int cp = 0; cp < 4; cp++) {
            const float2 lam2 = make_float2(s_lam[c0 + 2 * cp], s_lam[c0 + 2 * cp + 1]);
            #pragma unroll
            for (int s = 0; s < 4; s++) {
                float zx, zy;
                upk2(zx, zy, z[s][cp]);
                xv[s][cp].x = copysignf(fmaxf(fabsf(zx) - lam2.x, 0.f), zx);
                xv[s][cp].y = copysignf(fmaxf(fabsf(zy) - lam2.y, 0.f), zy);
            }
        }
        // publish x
        __syncwarp();
        #pragma unroll
        for (int cc = 0; cc < 8; cc++) {
            const int cp = cc >> 1;
            float4 v;
            if (cc & 1) v = make_float4(xv[0][cp].y, xv[1][cp].y, xv[2][cp].y, xv[3][cp].y);
            else        v = make_float4(xv[0][cp].x, xv[1][cp].x, xv[2][cp].x, xv[3][cp].x);
            HsW[(c0 + cc) * 4 + myslot] = v;
        }
        __syncwarp();
    }

    // ================= Phase 4: heads + outputs =================
    {
        float p[4][NAPP];
        #pragma unroll
        for (int n = 0; n < NAPP; n++) {
            #pragma unroll
            for (int s = 0; s < 4; s++) {
                float acc = 0.f;
                #pragma unroll
                for (int cp = 0; cp < 4; cp++) {
                    acc = fmaf(xv[s][cp].x, s_head[n * AA + c0 + 2 * cp], acc);
                    acc = fmaf(xv[s][cp].y, s_head[n * AA + c0 + 2 * cp + 1], acc);
                }
                acc += __shfl_xor_sync(FULL, acc, 1, 32);
                acc += __shfl_xor_sync(FULL, acc, 2, 32);
                acc += __shfl_xor_sync(FULL, acc, 4, 32);
                p[s][n] = acc;
            }
        }
        #pragma unroll
        for (int s = 0; s < 4; s++) {
            const int b = s0 + s;
            if (b < B) {
                if (cg == 0) {
                    float4 pw = make_float4(p[s][0] + s_headb[0], p[s][1] + s_headb[1],
                                            p[s][2] + s_headb[2], p[s][3] + s_headb[3]);
                    *reinterpret_cast<float4*>(out_power + (long)b * NAPP) = pw;
                }
                float4* xo = reinterpret_cast<float4*>(out_x + (long)b * AA + c0);
                xo[0] = make_float4(xv[s][0].x, xv[s][0].y, xv[s][1].x, xv[s][1].y);
                xo[1] = make_float4(xv[s][2].x, xv[s][2].y, xv[s][3].x, xv[s][3].y);
            }
        }
    }
}

extern "C" void kernel_launch(void* const* d_in, const int* in_sizes, int n_in,
                              void* d_out, int out_size)
{
    const float* y         = (const float*)d_in[0];
    const float* w_in      = (const float*)d_in[1];
    const float* b_in      = (const float*)d_in[2];
    const float* tau_param = (const float*)d_in[3];
    const float* W_rec     = (const float*)d_in[4];
    const float* ln_w      = (const float*)d_in[5];
    const float* ln_b      = (const float*)d_in[6];
    const float* Wx0       = (const float*)d_in[7];
    const float* bx0       = (const float*)d_in[8];
    const float* We        = (const float*)d_in[9];
    const float* be        = (const float*)d_in[10];
    const float* Wr        = (const float*)d_in[11];
    const float* thr       = (const float*)d_in[12];
    const float* head_W    = (const float*)d_in[13];
    const float* head_b    = (const float*)d_in[14];

    const int B = in_sizes[0] / WIN;

    float* out       = (float*)d_out;
    float* out_power = out;                      // (B, NAPP) first
    float* out_x     = out + (size_t)B * NAPP;   // (B, A) second

    // single merged prep launch
    {
        const int nBB = (B + 31) / 32;
        const int nYBlocks = nBB * ((WIN + 31) / 32);          // y tiles
        const int wTotal = KK * WIN * AA + KK * AA * AA + AA * AA;
        const int nWBlocks = (wTotal + 255) / 256;
        prep_all_kernel<<<nYBlocks + nWBlocks, 256>>>(y, We, Wr, Wx0, B, nBB, nYBlocks);
    }

    cudaFuncSetAttribute(pinn_main_kernel,
                         cudaFuncAttributeMaxDynamicSharedMemorySize,
                         (int)DYN_BYTES);

    const int grid = (B + SPC - 1) / SPC;
    pinn_main_kernel<<<grid, TPB, DYN_BYTES>>>(
        w_in, b_in, tau_param, W_rec, ln_w, ln_b,
        bx0, be, thr, head_W, head_b,
        out_power, out_x, B);
}